// round 1
// baseline (speedup 1.0000x reference)
#include <cuda_runtime.h>

#define TT 2048
#define BBATCH 4096
#define HH 64
#define NPAIR 16      // batch pairs per CTA (32 batch elems)
#define NTHREADS 256
#define NCTA 128

typedef unsigned long long u64;

static __device__ __forceinline__ u64 pk2(float x, float y){
    u64 r; asm("mov.b64 %0,{%1,%2};" : "=l"(r) : "f"(x), "f"(y)); return r;
}
static __device__ __forceinline__ void up2(u64 v, float &x, float &y){
    asm("mov.b64 {%0,%1},%2;" : "=f"(x), "=f"(y) : "l"(v));
}
static __device__ __forceinline__ u64 fma2(u64 a, u64 b, u64 c){
    u64 d; asm("fma.rn.f32x2 %0,%1,%2,%3;" : "=l"(d) : "l"(a), "l"(b), "l"(c)); return d;
}
static __device__ __forceinline__ u64 add2(u64 a, u64 b){
    u64 d; asm("add.rn.f32x2 %0,%1,%2;" : "=l"(d) : "l"(a), "l"(b)); return d;
}
static __device__ __forceinline__ u64 mul2(u64 a, u64 b){
    u64 d; asm("mul.rn.f32x2 %0,%1,%2;" : "=l"(d) : "l"(a), "l"(b)); return d;
}
static __device__ __forceinline__ u64 sub2(u64 a, u64 b){
    u64 d; asm("sub.rn.f32x2 %0,%1,%2;" : "=l"(d) : "l"(a), "l"(b)); return d;
}
static __device__ __forceinline__ u64 relu2(u64 a){
    float x, y; up2(a, x, y);
    return pk2(fmaxf(x, 0.f), fmaxf(y, 0.f));
}

__global__ __launch_bounds__(NTHREADS, 1)
void garch_pinn_kernel(
    const float* __restrict__ returns, const float* __restrict__ log_rv,
    const float* __restrict__ omega_p, const float* __restrict__ beta_p,
    const float* __restrict__ tau1_p, const float* __restrict__ tau2_p,
    const float* __restrict__ gamma_p, const float* __restrict__ xi_p,
    const float* __restrict__ phi_p, const float* __restrict__ d1_p,
    const float* __restrict__ d2_p, const float* __restrict__ mu_p,
    const float* __restrict__ W1, const float* __restrict__ b1,
    const float* __restrict__ W2, const float* __restrict__ b2,
    const float* __restrict__ W3, const float* __restrict__ b3_p,
    float* __restrict__ out)
{
    // weights duplicated into both f32x2 lanes so one LDS serves 2 batch elems
    __shared__ __align__(16) u64 sW2[HH * HH];     // [i][o], 32 KB
    __shared__ __align__(16) u64 sW1[3 * HH];
    __shared__ __align__(16) u64 sb1[HH];
    __shared__ __align__(16) u64 sb2[HH];
    __shared__ __align__(16) u64 sW3[HH];
    __shared__ __align__(16) u64 sh1[HH * NPAIR];      // [i][p] (transposed for bcast)
    __shared__ __align__(16) u64 spart[NPAIR * NPAIR]; // [oc][p]

    const int tid = threadIdx.x;
    const int p  = tid & 15;      // batch pair within CTA
    const int oc = tid >> 4;      // output chunk 0..15 (4 outputs each)
    const int o0 = oc * 4;

    for (int idx = tid; idx < HH * HH; idx += NTHREADS) { float w = W2[idx]; sW2[idx] = pk2(w, w); }
    for (int idx = tid; idx < 3 * HH;  idx += NTHREADS) { float w = W1[idx]; sW1[idx] = pk2(w, w); }
    if (tid < HH) {
        float v1 = b1[tid]; sb1[tid] = pk2(v1, v1);
        float v2 = b2[tid]; sb2[tid] = pk2(v2, v2);
        float v3 = W3[tid]; sW3[tid] = pk2(v3, v3);
    }

    const float omega = *omega_p, beta = *beta_p, tau1 = *tau1_p, tau2 = *tau2_p;
    const float gam = *gamma_p, xi = *xi_p, phi = *phi_p;
    const float d1 = *d1_p, d2 = *d2_p, mu = *mu_p, b3 = *b3_p;
    const u64 omega2 = pk2(omega, omega), beta2 = pk2(beta, beta);
    const u64 tau12 = pk2(tau1, tau1), tau22 = pk2(tau2, tau2);
    const u64 gam2 = pk2(gam, gam), xi2 = pk2(xi, xi), phi2 = pk2(phi, phi);
    const u64 d12 = pk2(d1, d1), d22 = pk2(d2, d2), mu2 = pk2(mu, mu);
    const u64 b32 = pk2(b3, b3);
    const u64 negone2 = pk2(-1.f, -1.f), c001 = pk2(0.01f, 0.01f);

    const long b0 = (long)blockIdx.x * (2 * NPAIR) + 2 * p;
    const float* retp = returns + b0 * TT;
    const float* lrvp = log_rv + b0 * TT;
    const long BT = (long)BBATCH * TT;
    float* outLH = out + b0 * TT;            // output order: (enh, log_x, z, u)
    float* outLX = out + BT + b0 * TT;
    float* outZ  = out + 2 * BT + b0 * TT;
    float* outU  = out + 3 * BT + b0 * TT;

    __syncthreads();

    u64 rc = pk2(retp[0], retp[TT]);
    u64 lc = pk2(lrvp[0], lrvp[TT]);
    u64 lh = lc;   // t=0: log_h0 = log(mean(exp(lrv0))) = lrv0

    const ulonglong2* w2v = reinterpret_cast<const ulonglong2*>(sW2) + 2 * oc;
    const u64* hcol = sh1 + p;

    for (int t = 0; t < TT; t++) {
        // ---- phase 1: elementwise measurement (redundant across oc groups) ----
        float lhx, lhy; up2(lh, lhx, lhy);
        u64 e = pk2(__expf(-0.5f * lhx), __expf(-0.5f * lhy));
        u64 z = mul2(sub2(rc, mu2), e);                 // (r-mu)/sqrt(exp(lh))
        u64 z2m1 = fma2(z, z, negone2);                 // z^2 - 1
        u64 delta = fma2(d22, z2m1, mul2(d12, z));
        u64 s = add2(fma2(phi2, lh, xi2), delta);       // xi + phi*lh + delta
        u64 u = sub2(lc, s);                            // lrv - s ; log_x == lrv

        // prefetch next step's inputs (hidden under layer1+layer2)
        const int tn = (t + 1 < TT) ? t + 1 : TT - 1;
        u64 rn = pk2(retp[tn], retp[TT + tn]);
        u64 ln = pk2(lrvp[tn], lrvp[TT + tn]);

        if (oc == 0) {
            float a, b;
            up2(z, a, b);  outZ[t] = a;  outZ[TT + t] = b;
            up2(u, a, b);  outU[t] = a;  outU[TT + t] = b;
            up2(lc, a, b); outLX[t] = a; outLX[TT + t] = b;
        }

        // ---- layer 1: [lh, z, u] @ W1 + b1, relu -> sh1[i][p] ----
        #pragma unroll
        for (int j = 0; j < 4; j++) {
            const int o = o0 + j;
            u64 a = sb1[o];
            a = fma2(sW1[o], lh, a);
            a = fma2(sW1[HH + o], z, a);
            a = fma2(sW1[2 * HH + o], u, a);
            sh1[o * NPAIR + p] = relu2(a);
        }
        __syncthreads();

        // ---- layer 2: 64x64, 4 outputs per thread, f32x2 over batch pair ----
        u64 a0 = sb2[o0], a1 = sb2[o0 + 1], a2 = sb2[o0 + 2], a3 = sb2[o0 + 3];
        #pragma unroll
        for (int i = 0; i < HH; i++) {
            u64 h = hcol[i * NPAIR];              // broadcast within oc-group
            ulonglong2 wA = w2v[i * 32];          // W2[i][o0..o0+1] duplicated
            ulonglong2 wB = w2v[i * 32 + 1];      // W2[i][o0+2..o0+3]
            a0 = fma2(h, wA.x, a0);
            a1 = fma2(h, wA.y, a1);
            a2 = fma2(h, wB.x, a2);
            a3 = fma2(h, wB.y, a3);
        }

        // ---- layer 3 partial: relu(h2) . W3 over this thread's 4 outputs ----
        u64 pt = mul2(relu2(a0), sW3[o0]);
        pt = fma2(relu2(a1), sW3[o0 + 1], pt);
        pt = fma2(relu2(a2), sW3[o0 + 2], pt);
        pt = fma2(relu2(a3), sW3[o0 + 3], pt);
        spart[oc * NPAIR + p] = pt;
        __syncthreads();

        // ---- reduce over 16 oc chunks (redundant, deterministic order) ----
        u64 nn = spart[p];
        #pragma unroll
        for (int cc = 1; cc < NPAIR; cc++) nn = add2(nn, spart[cc * NPAIR + p]);
        u64 enh = fma2(c001, add2(nn, b32), lh);   // lh + 0.01*(nn + b3)

        if (oc == 0) { float a, b; up2(enh, a, b); outLH[t] = a; outLH[TT + t] = b; }

        // ---- GARCH recurrence for next step ----
        u64 nl = fma2(beta2, enh, omega2);
        nl = fma2(tau12, z, nl);
        nl = fma2(tau22, z2m1, nl);
        lh = fma2(gam2, u, nl);
        rc = rn; lc = ln;
    }
}

extern "C" void kernel_launch(void* const* d_in, const int* in_sizes, int n_in,
                              void* d_out, int out_size)
{
    garch_pinn_kernel<<<NCTA, NTHREADS>>>(
        (const float*)d_in[0],  (const float*)d_in[1],
        (const float*)d_in[2],  (const float*)d_in[3],
        (const float*)d_in[4],  (const float*)d_in[5],
        (const float*)d_in[6],  (const float*)d_in[7],
        (const float*)d_in[8],  (const float*)d_in[9],
        (const float*)d_in[10], (const float*)d_in[11],
        (const float*)d_in[12], (const float*)d_in[13],
        (const float*)d_in[14], (const float*)d_in[15],
        (const float*)d_in[16], (const float*)d_in[17],
        (float*)d_out);
}

// round 2
// speedup vs baseline: 1.7729x; 1.7729x over previous
#include <cuda_runtime.h>

#define TT 2048
#define BB 4096
#define NTH 256
#define NCTA 128

typedef unsigned long long u64;

static __device__ __forceinline__ u64 pk2(float x, float y){
    u64 r; asm("mov.b64 %0,{%1,%2};" : "=l"(r) : "f"(x), "f"(y)); return r;
}
static __device__ __forceinline__ void up2(u64 v, float &x, float &y){
    asm("mov.b64 {%0,%1},%2;" : "=f"(x), "=f"(y) : "l"(v));
}
static __device__ __forceinline__ u64 fma2(u64 a, u64 b, u64 c){
    u64 d; asm("fma.rn.f32x2 %0,%1,%2,%3;" : "=l"(d) : "l"(a), "l"(b), "l"(c)); return d;
}
static __device__ __forceinline__ float pick4(float a, float b, float c, float d, int s){
    float x = (s & 1) ? b : a;
    float y = (s & 1) ? d : c;
    return (s & 2) ? y : x;
}

__global__ __launch_bounds__(NTH, 1)
void garch_pinn_kernel(
    const float* __restrict__ returns, const float* __restrict__ log_rv,
    const float* __restrict__ omega_p, const float* __restrict__ beta_p,
    const float* __restrict__ tau1_p, const float* __restrict__ tau2_p,
    const float* __restrict__ gamma_p, const float* __restrict__ xi_p,
    const float* __restrict__ phi_p, const float* __restrict__ d1_p,
    const float* __restrict__ d2_p, const float* __restrict__ mu_p,
    const float* __restrict__ W1, const float* __restrict__ b1,
    const float* __restrict__ W2, const float* __restrict__ b2,
    const float* __restrict__ W3, const float* __restrict__ b3_p,
    float* __restrict__ out)
{
    // per-warp h1 tile: [warp][bp][i] -> 16B = (dup(b_even), dup(b_odd))
    __shared__ __align__(16) float sh1[8][2][64][4];       // 16 KB
    // per-warp output staging: [warp][arr*4+b][33] (pad 33 -> conflict-free)
    __shared__ float obuf[8][16][33];                      // ~16.9 KB

    const int tid = threadIdx.x;
    const int w = tid >> 5;
    const int l = tid & 31;

    // ---- persistent W2 in registers: lane owns output columns l and l+32 ----
    u64 wreg[64];
    #pragma unroll
    for (int i = 0; i < 64; i++)
        wreg[i] = pk2(W2[i * 64 + l], W2[i * 64 + l + 32]);

    // layer-1 / layer-3 per-lane constants
    const float w1a0 = W1[0 * 64 + l],      w1a1 = W1[1 * 64 + l],      w1a2 = W1[2 * 64 + l];
    const float w1b0 = W1[0 * 64 + l + 32], w1b1 = W1[1 * 64 + l + 32], w1b2 = W1[2 * 64 + l + 32];
    const float b1a = b1[l], b1b = b1[l + 32];
    const float w3a = W3[l], w3b = W3[l + 32];
    const u64 b2pair = pk2(b2[l], b2[l + 32]);

    const float omega = *omega_p, beta = *beta_p, tau1 = *tau1_p, tau2 = *tau2_p;
    const float gam = *gamma_p, xi = *xi_p, phi = *phi_p;
    const float d1 = *d1_p, d2 = *d2_p, mu = *mu_p, b3 = *b3_p;

    // this warp's 4 batch chains
    const long bg = (long)blockIdx.x * 32 + w * 4;
    const float* rp = returns + bg * TT;
    const float* lp = log_rv + bg * TT;
    const long BT = (long)BB * TT;

    float lh[4], rcur[4], lcur[4];
    #pragma unroll
    for (int b = 0; b < 4; b++) {
        rcur[b] = rp[b * TT];
        lcur[b] = lp[b * TT];
        lh[b] = lcur[b];     // log(mean(exp(lrv0))) == lrv0
    }

    float4* sA = reinterpret_cast<float4*>(&sh1[w][0][0][0]);           // (bp*64+i)
    const ulonglong2* hA = reinterpret_cast<const ulonglong2*>(sA);
    float* obw = &obuf[w][0][0];

    for (int t = 0; t < TT; t++) {
        // prefetch next step inputs (L1-resident lines)
        const int tn = (t + 1 < TT) ? t + 1 : t;
        float rnxt[4], lnxt[4];
        #pragma unroll
        for (int b = 0; b < 4; b++) { rnxt[b] = rp[b * TT + tn]; lnxt[b] = lp[b * TT + tn]; }

        // ---- measurement (redundant in every lane; trivial flops) ----
        float z[4], u[4], z2m1[4];
        #pragma unroll
        for (int b = 0; b < 4; b++) {
            float e = __expf(-0.5f * lh[b]);
            z[b] = (rcur[b] - mu) * e;
            z2m1[b] = z[b] * z[b] - 1.0f;
            float s = xi + phi * lh[b] + d1 * z[b] + d2 * z2m1[b];
            u[b] = lcur[b] - s;          // log_x == lcur exactly
        }

        // ---- layer 1: this lane's two output rows, all 4 batches ----
        float va[4], vb[4];
        #pragma unroll
        for (int b = 0; b < 4; b++) {
            float t0 = fmaf(w1a0, lh[b], b1a);
            t0 = fmaf(w1a1, z[b], t0);
            t0 = fmaf(w1a2, u[b], t0);
            va[b] = fmaxf(t0, 0.0f);
            float t1 = fmaf(w1b0, lh[b], b1b);
            t1 = fmaf(w1b1, z[b], t1);
            t1 = fmaf(w1b2, u[b], t1);
            vb[b] = fmaxf(t1, 0.0f);
        }

        __syncwarp();
        // store duplicated pairs: row i=l (bp 0/1) and row i=l+32
        sA[l]           = make_float4(va[0], va[0], va[1], va[1]);
        sA[64 + l]      = make_float4(va[2], va[2], va[3], va[3]);
        sA[l + 32]      = make_float4(vb[0], vb[0], vb[1], vb[1]);
        sA[64 + l + 32] = make_float4(vb[2], vb[2], vb[3], vb[3]);
        __syncwarp();

        // ---- layer 2: 64x64, W2 from registers, h1 broadcast from smem ----
        u64 a0 = b2pair, a1 = b2pair, a2 = b2pair, a3 = b2pair;
        #pragma unroll
        for (int i = 0; i < 64; i++) {
            ulonglong2 p0 = hA[i];        // (dup h[i][b0], dup h[i][b1])
            ulonglong2 p1 = hA[64 + i];   // (dup h[i][b2], dup h[i][b3])
            a0 = fma2(p0.x, wreg[i], a0);
            a1 = fma2(p0.y, wreg[i], a1);
            a2 = fma2(p1.x, wreg[i], a2);
            a3 = fma2(p1.y, wreg[i], a3);
        }

        // ---- layer 3 partial + warp all-reduce over 64 outputs ----
        float tot[4];
        #pragma unroll
        for (int b = 0; b < 4; b++) {
            float x, y;
            u64 ab = (b == 0) ? a0 : (b == 1) ? a1 : (b == 2) ? a2 : a3;
            up2(ab, x, y);
            float part = fmaxf(x, 0.0f) * w3a + fmaxf(y, 0.0f) * w3b;
            #pragma unroll
            for (int s = 16; s > 0; s >>= 1)
                part += __shfl_xor_sync(0xffffffffu, part, s);
            tot[b] = part;
        }

        float enh[4];
        #pragma unroll
        for (int b = 0; b < 4; b++)
            enh[b] = fmaf(0.01f, tot[b] + b3, lh[b]);

        // ---- stage outputs (lanes 0..15: arr = l>>2, batch = l&3) ----
        {
            const int bsel = l & 3;
            float v_enh = pick4(enh[0], enh[1], enh[2], enh[3], bsel);
            float v_lx  = pick4(lcur[0], lcur[1], lcur[2], lcur[3], bsel);
            float v_z   = pick4(z[0], z[1], z[2], z[3], bsel);
            float v_u   = pick4(u[0], u[1], u[2], u[3], bsel);
            float v = pick4(v_enh, v_lx, v_z, v_u, l >> 2);
            if (l < 16) obw[l * 33 + (t & 31)] = v;
        }

        // ---- GARCH recurrence ----
        #pragma unroll
        for (int b = 0; b < 4; b++) {
            float nl = fmaf(beta, enh[b], omega);
            nl = fmaf(tau1, z[b], nl);
            nl = fmaf(tau2, z2m1[b], nl);
            lh[b] = fmaf(gam, u[b], nl);
            rcur[b] = rnxt[b];
            lcur[b] = lnxt[b];
        }

        // ---- coalesced flush every 32 steps ----
        if ((t & 31) == 31) {
            __syncwarp();
            const int t0 = t - 31;
            #pragma unroll
            for (int q = 0; q < 16; q++) {
                const int arr = q >> 2, bsel = q & 3;
                out[(long)arr * BT + (bg + bsel) * TT + t0 + l] = obw[q * 33 + l];
            }
            __syncwarp();
        }
    }
}

extern "C" void kernel_launch(void* const* d_in, const int* in_sizes, int n_in,
                              void* d_out, int out_size)
{
    garch_pinn_kernel<<<NCTA, NTH>>>(
        (const float*)d_in[0],  (const float*)d_in[1],
        (const float*)d_in[2],  (const float*)d_in[3],
        (const float*)d_in[4],  (const float*)d_in[5],
        (const float*)d_in[6],  (const float*)d_in[7],
        (const float*)d_in[8],  (const float*)d_in[9],
        (const float*)d_in[10], (const float*)d_in[11],
        (const float*)d_in[12], (const float*)d_in[13],
        (const float*)d_in[14], (const float*)d_in[15],
        (const float*)d_in[16], (const float*)d_in[17],
        (float*)d_out);
}

// round 3
// speedup vs baseline: 2.2851x; 1.2889x over previous
#include <cuda_runtime.h>

#define TT 2048
#define BB 4096
#define NTH 256
#define NCTA 128

typedef unsigned long long u64;

static __device__ __forceinline__ u64 pk2(float x, float y){
    u64 r; asm("mov.b64 %0,{%1,%2};" : "=l"(r) : "f"(x), "f"(y)); return r;
}
static __device__ __forceinline__ void up2(u64 v, float &x, float &y){
    asm("mov.b64 {%0,%1},%2;" : "=f"(x), "=f"(y) : "l"(v));
}
static __device__ __forceinline__ u64 swp2(u64 v){   // (lo,hi) -> (hi,lo)
    float x, y; up2(v, x, y); return pk2(y, x);
}
static __device__ __forceinline__ u64 fma2(u64 a, u64 b, u64 c){
    u64 d; asm("fma.rn.f32x2 %0,%1,%2,%3;" : "=l"(d) : "l"(a), "l"(b), "l"(c)); return d;
}
static __device__ __forceinline__ u64 add2(u64 a, u64 b){
    u64 d; asm("add.rn.f32x2 %0,%1,%2;" : "=l"(d) : "l"(a), "l"(b)); return d;
}
static __device__ __forceinline__ u64 mul2(u64 a, u64 b){
    u64 d; asm("mul.rn.f32x2 %0,%1,%2;" : "=l"(d) : "l"(a), "l"(b)); return d;
}
static __device__ __forceinline__ u64 relu2(u64 a){
    float x, y; up2(a, x, y);
    return pk2(fmaxf(x, 0.f), fmaxf(y, 0.f));
}
static __device__ __forceinline__ float pick4(float a, float b, float c, float d, int s){
    float x = (s & 1) ? b : a;
    float y = (s & 1) ? d : c;
    return (s & 2) ? y : x;
}

__global__ __launch_bounds__(NTH, 1)
void garch_pinn_kernel(
    const float* __restrict__ returns, const float* __restrict__ log_rv,
    const float* __restrict__ omega_p, const float* __restrict__ beta_p,
    const float* __restrict__ tau1_p, const float* __restrict__ tau2_p,
    const float* __restrict__ gamma_p, const float* __restrict__ xi_p,
    const float* __restrict__ phi_p, const float* __restrict__ d1_p,
    const float* __restrict__ d2_p, const float* __restrict__ mu_p,
    const float* __restrict__ W1, const float* __restrict__ b1,
    const float* __restrict__ W2, const float* __restrict__ b2,
    const float* __restrict__ W3, const float* __restrict__ b3_p,
    float* __restrict__ out)
{
    // per-warp h1 tile, NATURAL batch pairs: sA[i] = (h[i][b0..b3]); 1 KB/warp
    __shared__ __align__(16) float4 sh1[8][64];
    // per-warp output staging: [warp][arr*4+b][33] (pad 33 -> conflict-free)
    __shared__ float obuf[8][16][33];

    const int tid = threadIdx.x;
    const int w = tid >> 5;
    const int l = tid & 31;

    // ---- persistent W2 in registers: lane owns output columns l and l+32 ----
    u64 wreg[64];
    #pragma unroll
    for (int i = 0; i < 64; i++)
        wreg[i] = pk2(W2[i * 64 + l], W2[i * 64 + l + 32]);

    // layer-1 / layer-3 per-lane constants
    const float w1a0 = W1[0 * 64 + l],      w1a1 = W1[1 * 64 + l],      w1a2 = W1[2 * 64 + l];
    const float w1b0 = W1[0 * 64 + l + 32], w1b1 = W1[1 * 64 + l + 32], w1b2 = W1[2 * 64 + l + 32];
    const float b1a = b1[l], b1b = b1[l + 32];
    const u64 w3pair = pk2(W3[l], W3[l + 32]);
    const u64 b2pair = pk2(b2[l], b2[l + 32]);

    const float omega = *omega_p, beta = *beta_p, tau1 = *tau1_p, tau2 = *tau2_p;
    const float gam = *gamma_p, xi = *xi_p, phi = *phi_p;
    const float d1 = *d1_p, d2 = *d2_p, mu = *mu_p, b3 = *b3_p;

    // this warp's 4 batch chains
    const long bg = (long)blockIdx.x * 32 + w * 4;
    const float* rp = returns + bg * TT;
    const float* lp = log_rv + bg * TT;
    const long BT = (long)BB * TT;

    float lh[4], rcur[4], lcur[4];
    #pragma unroll
    for (int b = 0; b < 4; b++) {
        rcur[b] = rp[b * TT];
        lcur[b] = lp[b * TT];
        lh[b] = lcur[b];     // log(mean(exp(lrv0))) == lrv0
    }

    float4* sA = &sh1[w][0];
    const ulonglong2* hA = reinterpret_cast<const ulonglong2*>(sA);
    float* obw = &obuf[w][0][0];

    for (int t = 0; t < TT; t++) {
        // prefetch next step inputs (uniform per warp, L1-resident)
        const int tn = (t + 1 < TT) ? t + 1 : t;
        float rnxt[4], lnxt[4];
        #pragma unroll
        for (int b = 0; b < 4; b++) { rnxt[b] = rp[b * TT + tn]; lnxt[b] = lp[b * TT + tn]; }

        // ---- measurement (redundant in every lane; trivial flops) ----
        float z[4], u[4], z2m1[4];
        #pragma unroll
        for (int b = 0; b < 4; b++) {
            float e = __expf(-0.5f * lh[b]);
            z[b] = (rcur[b] - mu) * e;
            z2m1[b] = z[b] * z[b] - 1.0f;
            float s = xi + phi * lh[b] + d1 * z[b] + d2 * z2m1[b];
            u[b] = lcur[b] - s;          // log_x == lcur exactly
        }

        // ---- layer 1: this lane's two rows (l and l+32), all 4 batches ----
        float va[4], vb[4];
        #pragma unroll
        for (int b = 0; b < 4; b++) {
            float t0 = fmaf(w1a0, lh[b], b1a);
            t0 = fmaf(w1a1, z[b], t0);
            t0 = fmaf(w1a2, u[b], t0);
            va[b] = fmaxf(t0, 0.0f);
            float t1 = fmaf(w1b0, lh[b], b1b);
            t1 = fmaf(w1b1, z[b], t1);
            t1 = fmaf(w1b2, u[b], t1);
            vb[b] = fmaxf(t1, 0.0f);
        }

        __syncwarp();
        sA[l]      = make_float4(va[0], va[1], va[2], va[3]);   // natural pairs
        sA[l + 32] = make_float4(vb[0], vb[1], vb[2], vb[3]);
        __syncwarp();

        // ---- layer 2: 64x64. W2 in regs; h natural pairs + swapped accums ----
        // accA = (y[l][b0], y[l32][b1])   accB = (y[l][b1], y[l32][b0])
        // accC = (y[l][b2], y[l32][b3])   accD = (y[l][b3], y[l32][b2])
        u64 accA = b2pair, accB = b2pair, accC = b2pair, accD = b2pair;
        #pragma unroll
        for (int i = 0; i < 64; i++) {
            ulonglong2 P = hA[i];         // P.x=(b0,b1)  P.y=(b2,b3)  broadcast
            u64 s01 = swp2(P.x);
            u64 s23 = swp2(P.y);
            accA = fma2(P.x, wreg[i], accA);
            accB = fma2(s01, wreg[i], accB);
            accC = fma2(P.y, wreg[i], accC);
            accD = fma2(s23, wreg[i], accD);
        }

        // ---- layer 3 partial: relu + dot(W3) + component reassembly ----
        u64 ptA = mul2(relu2(accA), w3pair);   // (c[l][b0], c[l32][b1])
        u64 ptB = mul2(relu2(accB), w3pair);   // (c[l][b1], c[l32][b0])
        u64 ptC = mul2(relu2(accC), w3pair);
        u64 ptD = mul2(relu2(accD), w3pair);
        u64 pair01 = add2(ptA, swp2(ptB));     // (b0 part, b1 part)
        u64 pair23 = add2(ptC, swp2(ptD));

        // warp all-reduce (packed 2 batches per shfl)
        #pragma unroll
        for (int s = 16; s > 0; s >>= 1) {
            pair01 = add2(pair01, __shfl_xor_sync(0xffffffffu, pair01, s));
            pair23 = add2(pair23, __shfl_xor_sync(0xffffffffu, pair23, s));
        }

        float tot[4];
        up2(pair01, tot[0], tot[1]);
        up2(pair23, tot[2], tot[3]);

        float enh[4];
        #pragma unroll
        for (int b = 0; b < 4; b++)
            enh[b] = fmaf(0.01f, tot[b] + b3, lh[b]);

        // ---- stage outputs (lanes 0..15: arr = l>>2, batch = l&3) ----
        {
            const int bsel = l & 3;
            float v_enh = pick4(enh[0], enh[1], enh[2], enh[3], bsel);
            float v_lx  = pick4(lcur[0], lcur[1], lcur[2], lcur[3], bsel);
            float v_z   = pick4(z[0], z[1], z[2], z[3], bsel);
            float v_u   = pick4(u[0], u[1], u[2], u[3], bsel);
            float v = pick4(v_enh, v_lx, v_z, v_u, l >> 2);
            if (l < 16) obw[l * 33 + (t & 31)] = v;
        }

        // ---- GARCH recurrence ----
        #pragma unroll
        for (int b = 0; b < 4; b++) {
            float nl = fmaf(beta, enh[b], omega);
            nl = fmaf(tau1, z[b], nl);
            nl = fmaf(tau2, z2m1[b], nl);
            lh[b] = fmaf(gam, u[b], nl);
            rcur[b] = rnxt[b];
            lcur[b] = lnxt[b];
        }

        // ---- coalesced flush every 32 steps ----
        if ((t & 31) == 31) {
            __syncwarp();
            const int t0 = t - 31;
            #pragma unroll
            for (int q = 0; q < 16; q++) {
                const int arr = q >> 2, bsel = q & 3;
                out[(long)arr * BT + (bg + bsel) * TT + t0 + l] = obw[q * 33 + l];
            }
            __syncwarp();
        }
    }
}

extern "C" void kernel_launch(void* const* d_in, const int* in_sizes, int n_in,
                              void* d_out, int out_size)
{
    garch_pinn_kernel<<<NCTA, NTH>>>(
        (const float*)d_in[0],  (const float*)d_in[1],
        (const float*)d_in[2],  (const float*)d_in[3],
        (const float*)d_in[4],  (const float*)d_in[5],
        (const float*)d_in[6],  (const float*)d_in[7],
        (const float*)d_in[8],  (const float*)d_in[9],
        (const float*)d_in[10], (const float*)d_in[11],
        (const float*)d_in[12], (const float*)d_in[13],
        (const float*)d_in[14], (const float*)d_in[15],
        (const float*)d_in[16], (const float*)d_in[17],
        (float*)d_out);
}